// round 1
// baseline (speedup 1.0000x reference)
#include <cuda_runtime.h>

#define HID 50
#define GP  224      // gates padded: 4 gates * 56 j-slots (j<50 real)
#define K4N 13       // k padded 50->52, 4 per float4
#define BT  16       // batch rows per CTA
#define NTHREADS 256
#define GSTRIDE 225  // gates_s row stride (floats), odd -> conflict-friendly
#define HLSTRIDE 53

typedef unsigned long long u64;

// Packed fp32x2 FMA (Blackwell): 2 fp32 FMAs per instruction, exact fp32.
__device__ __forceinline__ void ffma2(u64& d, u64 a, u64 b) {
    asm("fma.rn.f32x2 %0, %1, %2, %3;" : "=l"(d) : "l"(a), "l"(b), "l"(d));
}

__device__ __forceinline__ float sigmoidf_(float x) {
    float e = __expf(-x);
    return __fdividef(1.f, 1.f + e);
}
__device__ __forceinline__ float tanhf_(float x) {
    float e = __expf(2.f * x);               // x->+inf: e=inf -> 1; x->-inf: e=0 -> -1
    return 1.f - __fdividef(2.f, e + 1.f);
}

__global__ void __launch_bounds__(NTHREADS, 1)
seq2seq_kernel(const float* __restrict__ source,
               const float* __restrict__ eWih, const float* __restrict__ eWhh,
               const float* __restrict__ eBih, const float* __restrict__ eBhh,
               const float* __restrict__ dWih, const float* __restrict__ dWhh,
               const float* __restrict__ dBih, const float* __restrict__ dBhh,
               const float* __restrict__ fcW,  const float* __restrict__ fcB,
               float* __restrict__ out, int S, int T)
{
    extern __shared__ char smem_raw[];
    float4* wenc  = (float4*)smem_raw;          // [K4N][GP] w[g][4k4..4k4+3]
    float4* wdec  = wenc + K4N * GP;
    float4* hpk   = wdec + K4N * GP;            // [K4N][BT] h[b][4k4..4k4+3]
    float*  gates = (float*)(hpk + K4N * BT);   // [BT][GSTRIDE]
    float*  hlin  = gates + BT * GSTRIDE;       // [BT][HLSTRIDE]
    float*  xdec  = hlin + BT * HLSTRIDE;       // [BT]
    float*  fcw   = xdec + BT;                  // [HID]
    float*  fcb   = fcw + HID;                  // [2]
    float*  srcs  = fcb + 2;                    // [BT][S]

    const int tid   = threadIdx.x;
    const int lane  = tid & 31;
    const int wrp   = tid >> 5;
    const int b     = lane & 15;      // GEMM role: batch row
    const int hh    = lane >> 4;      // GEMM role: gate half within warp chunk
    const int gbase = wrp * 28 + hh * 14;
    const int b0    = blockIdx.x * BT;

    // ---- build packed (transposed, padded) weight tiles, both phases at once
    for (int idx = tid; idx < K4N * GP; idx += NTHREADS) {
        int k4 = idx / GP, g = idx % GP;
        int gate = g / 56, j = g % 56;
        float4 ve = make_float4(0.f, 0.f, 0.f, 0.f), vd = ve;
        if (j < HID) {
            int row = gate * HID + j;
            #pragma unroll
            for (int c = 0; c < 4; c++) {
                int k = 4 * k4 + c;
                if (k < HID) {
                    ((float*)&ve)[c] = eWhh[row * HID + k];
                    ((float*)&vd)[c] = dWhh[row * HID + k];
                }
            }
        }
        wenc[idx] = ve;
        wdec[idx] = vd;
    }
    for (int i = tid; i < K4N * BT; i += NTHREADS) hpk[i] = make_float4(0.f, 0.f, 0.f, 0.f);
    if (tid < BT)  xdec[tid] = 0.f;
    if (tid < HID) fcw[tid] = fcW[tid];
    if (tid == 0)  fcb[0] = fcB[0];
    // stage the whole source slice for this CTA (coalesced, once)
    for (int bl = 0; bl < BT; bl++)
        for (int t = tid; t < S; t += NTHREADS)
            srcs[bl * S + t] = source[(size_t)(b0 + bl) * S + t];

    // ---- per-thread persistent state
    float biasr[14], wihr[14];       // GEMM role constants
    const int bu = tid & 15;         // update role: batch row
    const int j0 = tid >> 4;         // update role: base hidden index
    float c0 = 0.f, c1 = 0.f, c2 = 0.f, c3 = 0.f;

    #pragma unroll
    for (int i = 0; i < 14; i++) {
        int g = gbase + i, gate = g / 56, j = g % 56;
        if (j < HID) { int r = gate * HID + j; biasr[i] = eBih[r] + eBhh[r]; wihr[i] = eWih[r]; }
        else         { biasr[i] = 0.f; wihr[i] = 0.f; }
    }
    __syncthreads();

    // GEMM: gates[b][g] = bias + x*wih + sum_k h[b][k]*W[g][k], FFMA2 along k
    auto gemm = [&](const float4* wp, float x) {
        u64 acc[14];
        #pragma unroll
        for (int i = 0; i < 14; i++) {
            float lo = fmaf(x, wihr[i], biasr[i]);
            acc[i] = (u64)__float_as_uint(lo);           // hi lane starts at 0.0f
        }
        const ulonglong2* hp2 = (const ulonglong2*)hpk;
        const ulonglong2* wp2 = (const ulonglong2*)wp;
        #pragma unroll
        for (int k4 = 0; k4 < K4N; k4++) {
            ulonglong2 hv = hp2[k4 * BT + b];            // LDS.128, coalesced/broadcast
            #pragma unroll
            for (int i = 0; i < 14; i++) {
                ulonglong2 wv = wp2[k4 * GP + gbase + i]; // LDS.128, 2-addr broadcast
                ffma2(acc[i], wv.x, hv.x);
                ffma2(acc[i], wv.y, hv.y);
            }
        }
        #pragma unroll
        for (int i = 0; i < 14; i++) {
            u64 a = acc[i];
            float lo = __uint_as_float((unsigned)a);
            float hi = __uint_as_float((unsigned)(a >> 32));
            gates[b * GSTRIDE + gbase + i] = lo + hi;
        }
    };

    auto upd_one = [&](int j, float& c) {
        float gi = gates[bu * GSTRIDE + j];
        float gf = gates[bu * GSTRIDE + 56 + j];
        float gg = gates[bu * GSTRIDE + 112 + j];
        float go = gates[bu * GSTRIDE + 168 + j];
        float iv = sigmoidf_(gi);
        float fv = sigmoidf_(gf);
        float gv = tanhf_(gg);
        float ov = sigmoidf_(go);
        c = fmaf(fv, c, iv * gv);
        float h = ov * tanhf_(c);
        ((float*)hpk)[(j >> 2) * (BT * 4) + bu * 4 + (j & 3)] = h;
        hlin[bu * HLSTRIDE + j] = h;
    };

    auto update = [&]() {
        upd_one(j0,      c0);
        upd_one(j0 + 16, c1);
        upd_one(j0 + 32, c2);
        if (j0 < 2) upd_one(j0 + 48, c3);   // j = 48,49
    };

    // ================= encoder =================
    for (int t = 0; t < S; t++) {
        float x = srcs[b * S + t];
        gemm(wenc, x);
        __syncthreads();
        update();
        __syncthreads();
    }

    // ================= decoder =================
    #pragma unroll
    for (int i = 0; i < 14; i++) {
        int g = gbase + i, gate = g / 56, j = g % 56;
        if (j < HID) { int r = gate * HID + j; biasr[i] = dBih[r] + dBhh[r]; wihr[i] = dWih[r]; }
        else         { biasr[i] = 0.f; wihr[i] = 0.f; }
    }
    for (int t = 0; t < T; t++) {
        float x = xdec[b];
        gemm(wdec, x);
        __syncthreads();
        update();
        __syncthreads();
        if (wrp == 0) {  // fc: y[b] = h . fcW + fcb, 2 lanes per batch row
            float s = 0.f;
            #pragma unroll
            for (int jj = 0; jj < 25; jj++) {
                int j = hh * 25 + jj;
                s = fmaf(hlin[b * HLSTRIDE + j], fcw[j], s);
            }
            s += __shfl_xor_sync(0xffffffffu, s, 16);
            if (hh == 0) {
                float y = s + fcb[0];
                xdec[b] = y;                          // feed back as next input
                out[(size_t)(b0 + b) * T + t] = y;
            }
        }
        __syncthreads();
    }
}

extern "C" void kernel_launch(void* const* d_in, const int* in_sizes, int n_in,
                              void* d_out, int out_size)
{
    const float* source = (const float*)d_in[0];
    const float* eWih = (const float*)d_in[1];
    const float* eWhh = (const float*)d_in[2];
    const float* eBih = (const float*)d_in[3];
    const float* eBhh = (const float*)d_in[4];
    const float* dWih = (const float*)d_in[5];
    const float* dWhh = (const float*)d_in[6];
    const float* dBih = (const float*)d_in[7];
    const float* dBhh = (const float*)d_in[8];
    const float* fcW  = (const float*)d_in[9];
    const float* fcB  = (const float*)d_in[10];
    float* out = (float*)d_out;

    const int B = 2048;
    const int S = in_sizes[0] / B;   // 512
    const int T = out_size   / B;    // 256

    size_t sm = sizeof(float4) * (size_t)K4N * GP * 2
              + sizeof(float4) * (size_t)K4N * BT
              + sizeof(float)  * (size_t)(BT * GSTRIDE + BT * HLSTRIDE + BT + HID + 2)
              + sizeof(float)  * (size_t)BT * S;

    cudaFuncSetAttribute(seq2seq_kernel, cudaFuncAttributeMaxDynamicSharedMemorySize, (int)sm);
    seq2seq_kernel<<<B / BT, NTHREADS, sm>>>(source, eWih, eWhh, eBih, eBhh,
                                             dWih, dWhh, dBih, dBhh, fcW, fcB,
                                             out, S, T);
}